// round 2
// baseline (speedup 1.0000x reference)
#include <cuda_runtime.h>
#include <math.h>

// Shapes fixed by the problem definition.
#define T_DIM 64
#define U_DIM 142
#define I_DIM 4500
#define KSEL  10
#define SLOTS 5          // ceil(U_DIM / 32)
#define WARPS_PER_BLOCK 8

__global__ __launch_bounds__(WARPS_PER_BLOCK * 32)
void cf_topk_kernel(const float* __restrict__ qos,      // [T, U, I]
                    const float* __restrict__ uavg,     // [T, U]
                    const float* __restrict__ sim,      // [U, U]
                    const int*   __restrict__ uid,      // [B]
                    const int*   __restrict__ iid,      // [B]
                    const int*   __restrict__ tid_arr,  // [B]
                    float*       __restrict__ out,      // [B]
                    int B)
{
    const int warp = (blockIdx.x * blockDim.x + threadIdx.x) >> 5;
    const int lane = threadIdx.x & 31;
    if (warp >= B) return;

    const int t = tid_arr[warp];
    const int u = uid[warp];
    const int i = iid[warp];

    const float* qcol   = qos  + ((size_t)t * U_DIM) * I_DIM + i; // element v at stride I_DIM
    const float* simrow = sim  + (size_t)u * U_DIM;               // contiguous, L2-resident
    const float* avgrow = uavg + (size_t)t * U_DIM;               // contiguous, L2-resident

    // Each lane owns users v = lane + 32*s, s in [0,SLOTS)
    float m[SLOTS];   // masked similarity (selection key)
    float q[SLOTS];   // qos[t, v, i]
    float av[SLOTS];  // user_avg[t, v]

    #pragma unroll
    for (int s = 0; s < SLOTS; s++) {
        const int v = lane + 32 * s;
        if (v < U_DIM) {
            // Independent loads -> high MLP, hides DRAM latency of the strided gather
            const float qq = __ldg(qcol + (size_t)v * I_DIM);
            const float sv = __ldg(simrow + v);
            const float avv = __ldg(avgrow + v);
            q[s]  = qq;
            av[s] = avv;
            m[s]  = (qq > 0.0f) ? sv : 0.0f;   // item_rated mask
        } else {
            q[s] = 0.0f; av[s] = 0.0f;
            m[s] = -INFINITY;                  // never selected (142 >= K real candidates)
        }
    }

    float S = 0.0f;   // sum of selected sims (identical on all lanes)
    float C = 0.0f;   // per-lane partial of sum sim_k * (r_k - avg_v_k)

    #pragma unroll
    for (int k = 0; k < KSEL; k++) {
        // local argmax with JAX tie-break (strict > keeps the lower index: slot s
        // has index lane+32s, monotonically increasing in s)
        float bv = m[0];
        int   bi = lane;
        #pragma unroll
        for (int s = 1; s < SLOTS; s++) {
            if (m[s] > bv) { bv = m[s]; bi = lane + 32 * s; }
        }
        // warp butterfly reduce: larger value wins; equal values -> smaller index wins
        #pragma unroll
        for (int off = 16; off; off >>= 1) {
            const float ov = __shfl_xor_sync(0xffffffffu, bv, off);
            const int   oi = __shfl_xor_sync(0xffffffffu, bi, off);
            if (ov > bv || (ov == bv && oi < bi)) { bv = ov; bi = oi; }
        }
        S += bv;
        // Owning lane records the contribution and retires the slot.
        // Unrolled predicated compare avoids dynamic register indexing (no LMEM spill).
        if ((bi & 31) == lane) {
            const int os = bi >> 5;
            #pragma unroll
            for (int s = 0; s < SLOTS; s++) {
                if (s == os) {
                    C += bv * (q[s] - av[s]);
                    m[s] = -INFINITY;
                }
            }
        }
    }

    // warp-sum the contribution partials
    #pragma unroll
    for (int off = 16; off; off >>= 1)
        C += __shfl_xor_sync(0xffffffffu, C, off);

    if (lane == 0) {
        const float avg_u = __ldg(avgrow + u);
        float r = C / (S + 1e-8f);
        if (isnan(r)) r = 0.0f;                // nan_to_num
        out[warp] = avg_u + r;
    }
}

extern "C" void kernel_launch(void* const* d_in, const int* in_sizes, int n_in,
                              void* d_out, int out_size)
{
    const float* qos  = (const float*)d_in[0];  // qos_tensor [T,U,I] f32
    const float* uavg = (const float*)d_in[1];  // user_avg   [T,U]   f32
    const float* sim  = (const float*)d_in[2];  // user_sim_agg [U,U] f32
    const int*   uid  = (const int*)  d_in[3];  // user_id [B] i32
    const int*   iid  = (const int*)  d_in[4];  // item_id [B] i32
    const int*   tid  = (const int*)  d_in[5];  // time_id [B] i32
    // d_in[6] = top_k (scalar) — fixed to 10, compiled in.

    float* out = (float*)d_out;
    const int B = in_sizes[3];

    const int threads = WARPS_PER_BLOCK * 32;
    const int blocks  = (B + WARPS_PER_BLOCK - 1) / WARPS_PER_BLOCK;
    cf_topk_kernel<<<blocks, threads>>>(qos, uavg, sim, uid, iid, tid, out, B);
}

// round 4
// speedup vs baseline: 1.5127x; 1.5127x over previous
#include <cuda_runtime.h>
#include <math.h>

// Shapes fixed by the problem definition.
#define T_DIM 64
#define U_DIM 142
#define I_DIM 4500
#define KSEL  10
#define SLOTS 5          // ceil(U_DIM / 32)
#define WARPS_PER_BLOCK 8

// Order-preserving float32 <-> uint32 mapping (monotone for all finite floats).
__device__ __forceinline__ unsigned f2ord(float f) {
    unsigned u = __float_as_uint(f);
    return (u & 0x80000000u) ? ~u : (u | 0x80000000u);
}
__device__ __forceinline__ float ord2f(unsigned s) {
    unsigned u = (s & 0x80000000u) ? (s ^ 0x80000000u) : ~s;
    return __uint_as_float(u);
}

// Compare-exchange: bigger key to lower index (descending sort).
#define CE(a, b) { unsigned long long _t; if (kk[a] < kk[b]) { _t = kk[a]; kk[a] = kk[b]; kk[b] = _t; } }

__global__ __launch_bounds__(WARPS_PER_BLOCK * 32)
void cf_topk_kernel(const float* __restrict__ qos,      // [T, U, I]
                    const float* __restrict__ uavg,     // [T, U]
                    const float* __restrict__ sim,      // [U, U]
                    const int*   __restrict__ uid,      // [B]
                    const int*   __restrict__ iid,      // [B]
                    const int*   __restrict__ tid_arr,  // [B]
                    float*       __restrict__ out,      // [B]
                    int B)
{
    const int warp = (blockIdx.x * blockDim.x + threadIdx.x) >> 5;
    const int lane = threadIdx.x & 31;
    if (warp >= B) return;

    const int t = tid_arr[warp];
    const int u = uid[warp];
    const int i = iid[warp];

    const float* qcol   = qos  + ((size_t)t * U_DIM) * I_DIM + i; // user v at stride I_DIM
    const float* simrow = sim  + (size_t)u * U_DIM;               // contiguous, L2-resident
    const float* avgrow = uavg + (size_t)t * U_DIM;               // contiguous, L2-resident

    // Each lane owns users v = lane + 32*s. Packed key: [f2ord(masked sim) | ~v].
    // Max key == max sim, tie -> lowest user index (matches JAX stable top_k).
    // Sentinel 0 is below every real key (f2ord(-1.0f) = 0x407FFFFF > 0).
    unsigned long long kk[SLOTS];

    #pragma unroll
    for (int s = 0; s < SLOTS; s++) {
        const int v = lane + 32 * s;
        if (v < U_DIM) {
            const float qq = __ldg(qcol + (size_t)v * I_DIM);   // DRAM gather (dominant traffic)
            const float sv = __ldg(simrow + v);                 // cache-resident
            const float mv = (qq > 0.0f) ? sv : 0.0f;           // item_rated mask
            kk[s] = ((unsigned long long)f2ord(mv) << 32) | (unsigned)(~v);
        } else {
            kk[s] = 0ull;
        }
    }

    // Sort this lane's 5 keys descending (bubble network, 10 CE, branch-free-ish).
    CE(0,1) CE(1,2) CE(2,3) CE(3,4)
    CE(0,1) CE(1,2) CE(2,3)
    CE(0,1) CE(1,2)
    CE(0,1)

    float S = 0.0f;   // sum of selected sims (computed identically on all lanes)
    float C = 0.0f;   // lane 0 accumulates sum sim_k * (r_k - avg_v_k)

    #pragma unroll
    for (int k = 0; k < KSEL; k++) {
        const unsigned hi = (unsigned)(kk[0] >> 32);
        const unsigned lo = (unsigned)kk[0];

        // Warp max in two REDUX ops: value first, then ~index among value-holders.
        const unsigned him = __reduce_max_sync(0xffffffffu, hi);
        const unsigned cand = (hi == him) ? lo : 0u;
        const unsigned lom = __reduce_max_sync(0xffffffffu, cand);

        const float val = ord2f(him);
        S += val;

        // Exactly one lane owns the winner (user indices are unique) -> pop its queue.
        if (hi == him && lo == lom) {
            kk[0] = kk[1]; kk[1] = kk[2]; kk[2] = kk[3]; kk[3] = kk[4]; kk[4] = 0ull;
        }

        // Lane 0 fetches r_v and avg_v for the selected user (L1/L2 hot) and accumulates.
        if (lane == 0) {
            const int v = (int)(~lom);
            const float qq  = __ldg(qcol + (size_t)v * I_DIM);
            const float avv = __ldg(avgrow + v);
            C += val * (qq - avv);
        }
    }

    if (lane == 0) {
        const float avg_u = __ldg(avgrow + u);
        float r = C / (S + 1e-8f);
        if (isnan(r)) r = 0.0f;                // nan_to_num
        out[warp] = avg_u + r;
    }
}

extern "C" void kernel_launch(void* const* d_in, const int* in_sizes, int n_in,
                              void* d_out, int out_size)
{
    const float* qos  = (const float*)d_in[0];  // qos_tensor [T,U,I] f32
    const float* uavg = (const float*)d_in[1];  // user_avg   [T,U]   f32
    const float* sim  = (const float*)d_in[2];  // user_sim_agg [U,U] f32
    const int*   uid  = (const int*)  d_in[3];  // user_id [B] i32
    const int*   iid  = (const int*)  d_in[4];  // item_id [B] i32
    const int*   tid  = (const int*)  d_in[5];  // time_id [B] i32
    // d_in[6] = top_k (scalar) — fixed to 10, compiled in.

    float* out = (float*)d_out;
    const int B = in_sizes[3];

    const int threads = WARPS_PER_BLOCK * 32;
    const int blocks  = (B + WARPS_PER_BLOCK - 1) / WARPS_PER_BLOCK;
    cf_topk_kernel<<<blocks, threads>>>(qos, uavg, sim, uid, iid, tid, out, B);
}